// round 12
// baseline (speedup 1.0000x reference)
#include <cuda_runtime.h>
#include <cstdint>

#define NR 16384
#define PITCH 36            // floats per smem row (128B data + 16B pad)
#define SFL (2 * 128 * PITCH)   // floats per stage (A tile + B tile) = 9216

__device__ float g_T[(size_t)128 * NR];     // Tt[j][r] = (X@W)[r][j], tf32-rounded
__device__ float g_H[(size_t)NR * 128];     // A @ T
__device__ float g_ps[128 * 128], g_pq[128 * 128];
__device__ float g_mean[128], g_scale[128], g_beta2[128];

__device__ __forceinline__ uint32_t s2u(const void* p) {
    uint32_t a;
    asm("{ .reg .u64 t; cvta.to.shared.u64 t, %1; cvt.u32.u64 %0, t; }" : "=r"(a) : "l"(p));
    return a;
}

// ---------------- k1: Tt = round_tf32((X @ W)^T) ----------------
__global__ void k_xw(const float* __restrict__ X, const float* __restrict__ W) {
    extern __shared__ float sm[];
    float* ws = sm;              // [128*128] W
    float* xs = sm + 16384;      // [128] one row of X
    float* tl = sm + 16512;      // [128*33] transpose staging
    int j = threadIdx.x;
    for (int i = j; i < 16384; i += 128) ws[i] = W[i];
    int r0 = blockIdx.x * 32;
    __syncthreads();
    for (int rr = 0; rr < 32; rr++) {
        xs[j] = X[(size_t)(r0 + rr) * 128 + j];
        __syncthreads();
        float acc = 0.f;
        #pragma unroll 16
        for (int k = 0; k < 128; k++) acc += xs[k] * ws[k * 128 + j];
        uint32_t u;
        asm("cvt.rna.tf32.f32 %0, %1;" : "=r"(u) : "f"(acc));
        tl[j * 33 + rr] = __uint_as_float(u);
        __syncthreads();
    }
    for (int idx = j; idx < 4096; idx += 128) {   // coalesced 128B writes per g_T row
        int jj = idx >> 5, r2 = idx & 31;
        g_T[(size_t)jj * NR + r0 + r2] = tl[jj * 33 + r2];
    }
}

// ---------------- k2: H = A @ T via mma.sync tf32 ----------------
__global__ void __launch_bounds__(128, 1) k_gemm(const float* __restrict__ A) {
    extern __shared__ float smem[];
    int tid = threadIdx.x, wid = tid >> 5, lid = tid & 31;
    int gid = lid >> 2, tig = lid & 3;
    const int m0 = blockIdx.x * 128;
    const int wm = (wid & 1) * 64;      // warp tile 64x64
    const int wn = (wid >> 1) * 64;

    // async-load chunk ch into stage st. Layout: per stage, A[128][PITCH] then B[128][PITCH].
    auto load = [&](int ch, int st) {
        uint32_t base = s2u(smem) + (uint32_t)st * SFL * 4u;
        #pragma unroll
        for (int it = 0; it < 16; it++) {
            int u = tid + it * 128;                 // 2048 16B-segments total
            int half = u >> 10;                     // 0 = A, 1 = B
            int v = u & 1023, row = v >> 3, seg = v & 7;
            uint32_t dst = base + ((half ? 128u * PITCH : 0u) + (uint32_t)row * PITCH + seg * 4u) * 4u;
            const float* gp = half
                ? (g_T + (size_t)row * NR + (size_t)ch * 32 + seg * 4)
                : (A   + (size_t)(m0 + row) * NR + (size_t)ch * 32 + seg * 4);
            asm volatile("cp.async.cg.shared.global [%0], [%1], 16;" :: "r"(dst), "l"(gp));
        }
        asm volatile("cp.async.commit_group;" ::: "memory");
    };

    float c[4][8][4];
    #pragma unroll
    for (int i = 0; i < 4; i++)
        #pragma unroll
        for (int j = 0; j < 8; j++)
            c[i][j][0] = c[i][j][1] = c[i][j][2] = c[i][j][3] = 0.f;

    load(0, 0); load(1, 1); load(2, 2);

    for (int ch = 0; ch < 512; ch++) {
        asm volatile("cp.async.wait_group 2;" ::: "memory");
        __syncthreads();
        if (ch + 3 < 512) load(ch + 3, (ch + 3) & 3);
        else asm volatile("cp.async.commit_group;" ::: "memory");

        const float* sA = smem + (ch & 3) * SFL;
        const float* sB = sA + 128 * PITCH;
        #pragma unroll
        for (int k0 = 0; k0 < 32; k0 += 8) {
            uint32_t a[4][4], b[8][2];
            #pragma unroll
            for (int i = 0; i < 4; i++) {
                int r = wm + i * 16 + gid;
                a[i][0] = __float_as_uint(sA[r * PITCH + k0 + tig]);
                a[i][1] = __float_as_uint(sA[(r + 8) * PITCH + k0 + tig]);
                a[i][2] = __float_as_uint(sA[r * PITCH + k0 + tig + 4]);
                a[i][3] = __float_as_uint(sA[(r + 8) * PITCH + k0 + tig + 4]);
            }
            #pragma unroll
            for (int j = 0; j < 8; j++) {
                int n = wn + j * 8 + gid;
                b[j][0] = __float_as_uint(sB[n * PITCH + k0 + tig]);
                b[j][1] = __float_as_uint(sB[n * PITCH + k0 + tig + 4]);
            }
            #pragma unroll
            for (int i = 0; i < 4; i++)
                #pragma unroll
                for (int j = 0; j < 8; j++)
                    asm volatile(
                        "mma.sync.aligned.m16n8k8.row.col.f32.tf32.tf32.f32 "
                        "{%0,%1,%2,%3}, {%4,%5,%6,%7}, {%8,%9}, {%0,%1,%2,%3};"
                        : "+f"(c[i][j][0]), "+f"(c[i][j][1]),
                          "+f"(c[i][j][2]), "+f"(c[i][j][3])
                        : "r"(a[i][0]), "r"(a[i][1]), "r"(a[i][2]), "r"(a[i][3]),
                          "r"(b[j][0]), "r"(b[j][1]));
        }
    }

    // epilogue: accumulators -> g_H (float2 stores, cols are even)
    #pragma unroll
    for (int i = 0; i < 4; i++) {
        #pragma unroll
        for (int j = 0; j < 8; j++) {
            int row = m0 + wm + i * 16 + gid;
            int col = wn + j * 8 + tig * 2;
            *(float2*)&g_H[(size_t)row * 128 + col]       = make_float2(c[i][j][0], c[i][j][1]);
            *(float2*)&g_H[(size_t)(row + 8) * 128 + col] = make_float2(c[i][j][2], c[i][j][3]);
        }
    }
}

// ---------------- k3: per-block column partial sums (deterministic) ----------------
__global__ void k_stats() {
    int b = blockIdx.x, t = threadIdx.x;
    const float* p = g_H + (size_t)b * 128 * 128 + t;
    float s = 0.f, q = 0.f;
    #pragma unroll 8
    for (int r = 0; r < 128; r++) { float v = p[(size_t)r * 128]; s += v; q += v * v; }
    g_ps[b * 128 + t] = s;
    g_pq[b * 128 + t] = q;
}

// ---------------- k4: finalize mean / scale ----------------
__global__ void k_fin(const float* __restrict__ gamma, const float* __restrict__ beta) {
    int j = threadIdx.x;
    float s = 0.f, q = 0.f;
    for (int b = 0; b < 128; b++) { s += g_ps[b * 128 + j]; q += g_pq[b * 128 + j]; }
    float m = s * (1.f / NR);
    float var = q * (1.f / NR) - m * m;
    g_mean[j] = m;
    g_scale[j] = gamma[j] * rsqrtf(var + 1e-5f);
    g_beta2[j] = beta[j];
}

// ---------------- k5: BN + LeakyReLU ----------------
__global__ void k_apply(float* __restrict__ out) {
    size_t i = (size_t)blockIdx.x * blockDim.x + threadIdx.x;   // float4 units
    int c = ((int)(i & 31)) * 4;
    float4 h = ((const float4*)g_H)[i];
    float4 r; float t;
    t = (h.x - g_mean[c+0]) * g_scale[c+0] + g_beta2[c+0]; r.x = t >= 0.f ? t : 0.2f * t;
    t = (h.y - g_mean[c+1]) * g_scale[c+1] + g_beta2[c+1]; r.y = t >= 0.f ? t : 0.2f * t;
    t = (h.z - g_mean[c+2]) * g_scale[c+2] + g_beta2[c+2]; r.z = t >= 0.f ? t : 0.2f * t;
    t = (h.w - g_mean[c+3]) * g_scale[c+3] + g_beta2[c+3]; r.w = t >= 0.f ? t : 0.2f * t;
    ((float4*)out)[i] = r;
}

extern "C" void kernel_launch(void* const* d_in, const int* in_sizes, int n_in,
                              void* d_out, int out_size) {
    const float* x     = (const float*)d_in[0];
    const float* A     = (const float*)d_in[1];
    const float* W     = (const float*)d_in[2];
    // d_in[3] = bias b: per-column constant, cancels exactly under BatchNorm -> unused
    const float* gamma = (const float*)d_in[4];
    const float* beta  = (const float*)d_in[5];
    float* out = (float*)d_out;

    cudaFuncSetAttribute(k_xw,   cudaFuncAttributeMaxDynamicSharedMemorySize, 82944);
    cudaFuncSetAttribute(k_gemm, cudaFuncAttributeMaxDynamicSharedMemorySize, 4 * SFL * 4);

    k_xw   <<<512, 128, 82944>>>(x, W);
    k_gemm <<<128, 128, 4 * SFL * 4>>>(A);
    k_stats<<<128, 128>>>();
    k_fin  <<<1, 128>>>(gamma, beta);
    k_apply<<<2048, 256>>>(out);
}

// round 13
// speedup vs baseline: 1.1716x; 1.1716x over previous
#include <cuda_runtime.h>
#include <cuda_fp16.h>
#include <cstdint>

#define NR 16384
// per-stage smem layout (bytes): A fp32 tile, B fp16 tile, A fp16 tile
#define A32OFF 0
#define B16OFF 18432
#define A16OFF 28672
#define STGB   38912        // stage size: 128*144 + 128*80 + 128*80

__device__ __half g_Th[(size_t)128 * NR];   // Tt[j][r] = fp16((X@W)[r][j]), K-major
__device__ float  g_H[(size_t)NR * 128];    // A @ T
__device__ float  g_ps[128 * 128], g_pq[128 * 128];
__device__ float  g_mean[128], g_scale[128], g_beta2[128];

__device__ __forceinline__ uint32_t s2u(const void* p) {
    uint32_t a;
    asm("{ .reg .u64 t; cvta.to.shared.u64 t, %1; cvt.u32.u64 %0, t; }" : "=r"(a) : "l"(p));
    return a;
}

// ---------------- k1: Tt = fp16((X @ W)^T) ----------------
__global__ void k_xw(const float* __restrict__ X, const float* __restrict__ W) {
    extern __shared__ float sm[];
    float* ws = sm;              // [128*128] W
    float* xs = sm + 16384;      // [128] one row of X
    float* tl = sm + 16512;      // [128*33] transpose staging
    int j = threadIdx.x;
    for (int i = j; i < 16384; i += 128) ws[i] = W[i];
    int r0 = blockIdx.x * 32;
    __syncthreads();
    for (int rr = 0; rr < 32; rr++) {
        xs[j] = X[(size_t)(r0 + rr) * 128 + j];
        __syncthreads();
        float acc = 0.f;
        #pragma unroll 16
        for (int k = 0; k < 128; k++) acc += xs[k] * ws[k * 128 + j];
        tl[j * 33 + rr] = acc;
        __syncthreads();
    }
    for (int idx = j; idx < 4096; idx += 128) {   // coalesced half writes per g_Th row
        int jj = idx >> 5, r2 = idx & 31;
        g_Th[(size_t)jj * NR + r0 + r2] = __float2half_rn(tl[jj * 33 + r2]);
    }
}

// ---------------- k2: H = A @ T via fp16 mma.sync (fp32 accum) ----------------
__global__ void __launch_bounds__(256, 1) k_gemm(const float* __restrict__ A) {
    extern __shared__ __align__(16) char smc[];
    int tid = threadIdx.x, wid = tid >> 5, lid = tid & 31;
    int gid = lid >> 2, tig = lid & 3;
    const int m0 = blockIdx.x * 128;
    const int wm = (wid & 1) * 64;      // warp tile 64x32, warps 2(M) x 4(N)
    const int wn = (wid >> 1) * 32;

    // async-load chunk ch (K=32) into stage st: A fp32 (16 KB) + B fp16 (8 KB)
    auto load = [&](int ch, int st) {
        uint32_t base = s2u(smc) + (uint32_t)st * STGB;
        #pragma unroll
        for (int it = 0; it < 6; it++) {
            int u = tid + it * 256;
            if (u < 1024) {                             // A: 1024 x 16B
                int row = u >> 3, s = u & 7;
                uint32_t dst = base + A32OFF + row * 144 + s * 16;
                const float* gp = A + (size_t)(m0 + row) * NR + (size_t)ch * 32 + s * 4;
                asm volatile("cp.async.cg.shared.global [%0], [%1], 16;" :: "r"(dst), "l"(gp));
            } else {                                    // B: 512 x 16B
                int v = u - 1024, n = v >> 2, s = v & 3;
                uint32_t dst = base + B16OFF + n * 80 + s * 16;
                const __half* gp = g_Th + (size_t)n * NR + (size_t)ch * 32 + s * 8;
                asm volatile("cp.async.cg.shared.global [%0], [%1], 16;" :: "r"(dst), "l"(gp));
            }
        }
        asm volatile("cp.async.commit_group;" ::: "memory");
    };

    float c[4][4][4];
    #pragma unroll
    for (int i = 0; i < 4; i++)
        #pragma unroll
        for (int j = 0; j < 4; j++)
            c[i][j][0] = c[i][j][1] = c[i][j][2] = c[i][j][3] = 0.f;

    load(0, 0); load(1, 1); load(2, 2);

    for (int ch = 0; ch < 512; ch++) {
        const int st = ch & 3;
        const char* sb = smc + st * STGB;
        asm volatile("cp.async.wait_group 2;" ::: "memory");
        __syncthreads();                                  // stage st ready; st-1 consumed

        if (ch + 3 < 512) load(ch + 3, (ch + 3) & 3);
        else asm volatile("cp.async.commit_group;" ::: "memory");

        // convert A fp32 -> fp16 (1024 segs, 4 per thread)
        #pragma unroll
        for (int it = 0; it < 4; it++) {
            int v = tid + it * 256, row = v >> 3, s = v & 7;
            float4 f = *(const float4*)(sb + A32OFF + row * 144 + s * 16);
            __half2 h0 = __floats2half2_rn(f.x, f.y);
            __half2 h1 = __floats2half2_rn(f.z, f.w);
            uint2 u;
            u.x = *reinterpret_cast<unsigned*>(&h0);
            u.y = *reinterpret_cast<unsigned*>(&h1);
            *(uint2*)(const_cast<char*>(sb) + A16OFF + row * 80 + s * 8) = u;
        }
        __syncthreads();

        #pragma unroll
        for (int ks = 0; ks < 2; ks++) {                  // two K=16 steps
            uint32_t a[4][4], b[4][2];
            #pragma unroll
            for (int i = 0; i < 4; i++) {
                int r = wm + i * 16 + gid;
                const char* pa = sb + A16OFF + ks * 32 + tig * 4;
                a[i][0] = *(const uint32_t*)(pa + r * 80);
                a[i][1] = *(const uint32_t*)(pa + (r + 8) * 80);
                a[i][2] = *(const uint32_t*)(pa + r * 80 + 16);
                a[i][3] = *(const uint32_t*)(pa + (r + 8) * 80 + 16);
            }
            #pragma unroll
            for (int j = 0; j < 4; j++) {
                int n = wn + j * 8 + gid;
                const char* pb = sb + B16OFF + n * 80 + ks * 32 + tig * 4;
                b[j][0] = *(const uint32_t*)(pb);
                b[j][1] = *(const uint32_t*)(pb + 16);
            }
            #pragma unroll
            for (int i = 0; i < 4; i++)
                #pragma unroll
                for (int j = 0; j < 4; j++)
                    asm volatile(
                        "mma.sync.aligned.m16n8k16.row.col.f32.f16.f16.f32 "
                        "{%0,%1,%2,%3}, {%4,%5,%6,%7}, {%8,%9}, {%0,%1,%2,%3};"
                        : "+f"(c[i][j][0]), "+f"(c[i][j][1]),
                          "+f"(c[i][j][2]), "+f"(c[i][j][3])
                        : "r"(a[i][0]), "r"(a[i][1]), "r"(a[i][2]), "r"(a[i][3]),
                          "r"(b[j][0]), "r"(b[j][1]));
        }
    }

    // epilogue: accumulators -> g_H
    #pragma unroll
    for (int i = 0; i < 4; i++) {
        #pragma unroll
        for (int j = 0; j < 4; j++) {
            int row = m0 + wm + i * 16 + gid;
            int col = wn + j * 8 + tig * 2;
            *(float2*)&g_H[(size_t)row * 128 + col]       = make_float2(c[i][j][0], c[i][j][1]);
            *(float2*)&g_H[(size_t)(row + 8) * 128 + col] = make_float2(c[i][j][2], c[i][j][3]);
        }
    }
}

// ---------------- k3: per-block column partial sums (deterministic) ----------------
__global__ void k_stats() {
    int b = blockIdx.x, t = threadIdx.x;
    const float* p = g_H + (size_t)b * 128 * 128 + t;
    float s = 0.f, q = 0.f;
    #pragma unroll 8
    for (int r = 0; r < 128; r++) { float v = p[(size_t)r * 128]; s += v; q += v * v; }
    g_ps[b * 128 + t] = s;
    g_pq[b * 128 + t] = q;
}

// ---------------- k4: finalize mean / scale ----------------
__global__ void k_fin(const float* __restrict__ gamma, const float* __restrict__ beta) {
    int j = threadIdx.x;
    float s = 0.f, q = 0.f;
    #pragma unroll 16
    for (int b = 0; b < 128; b++) { s += g_ps[b * 128 + j]; q += g_pq[b * 128 + j]; }
    float m = s * (1.f / NR);
    float var = q * (1.f / NR) - m * m;
    g_mean[j] = m;
    g_scale[j] = gamma[j] * rsqrtf(var + 1e-5f);
    g_beta2[j] = beta[j];
}

// ---------------- k5: BN + LeakyReLU ----------------
__global__ void k_apply(float* __restrict__ out) {
    size_t i = (size_t)blockIdx.x * blockDim.x + threadIdx.x;   // float4 units
    int c = ((int)(i & 31)) * 4;
    float4 h = ((const float4*)g_H)[i];
    float4 r; float t;
    t = (h.x - g_mean[c+0]) * g_scale[c+0] + g_beta2[c+0]; r.x = t >= 0.f ? t : 0.2f * t;
    t = (h.y - g_mean[c+1]) * g_scale[c+1] + g_beta2[c+1]; r.y = t >= 0.f ? t : 0.2f * t;
    t = (h.z - g_mean[c+2]) * g_scale[c+2] + g_beta2[c+2]; r.z = t >= 0.f ? t : 0.2f * t;
    t = (h.w - g_mean[c+3]) * g_scale[c+3] + g_beta2[c+3]; r.w = t >= 0.f ? t : 0.2f * t;
    ((float4*)out)[i] = r;
}

extern "C" void kernel_launch(void* const* d_in, const int* in_sizes, int n_in,
                              void* d_out, int out_size) {
    const float* x     = (const float*)d_in[0];
    const float* A     = (const float*)d_in[1];
    const float* W     = (const float*)d_in[2];
    // d_in[3] = bias b: per-column constant, cancels exactly under BatchNorm -> unused
    const float* gamma = (const float*)d_in[4];
    const float* beta  = (const float*)d_in[5];
    float* out = (float*)d_out;

    cudaFuncSetAttribute(k_xw,   cudaFuncAttributeMaxDynamicSharedMemorySize, 82944);
    cudaFuncSetAttribute(k_gemm, cudaFuncAttributeMaxDynamicSharedMemorySize, 4 * STGB);

    k_xw   <<<512, 128, 82944>>>(x, W);
    k_gemm <<<128, 256, 4 * STGB>>>(A);
    k_stats<<<128, 128>>>();
    k_fin  <<<1, 128>>>(gamma, beta);
    k_apply<<<2048, 256>>>(out);
}

// round 14
// speedup vs baseline: 1.1835x; 1.0102x over previous
#include <cuda_runtime.h>
#include <cuda_fp16.h>
#include <cstdint>

#define NR 16384
// per-stage smem layout (bytes)
#define A32OFF 0            // 128 rows x 144B (32 fp32 + 16B pad)
#define B16OFF 18432        // 128 rows x 80B  (32 fp16 + 16B pad)
#define A16OFF 28672        // 128 rows x 80B
#define STGB   38912

__device__ __half g_Th[(size_t)128 * NR];   // Tt[j][r] = fp16((X@W)[r][j]), K-major
__device__ float  g_H[(size_t)NR * 128];    // A @ T
__device__ float  g_ps[128 * 128], g_pq[128 * 128];
__device__ float  g_mean[128], g_scale[128], g_beta2[128];

__device__ __forceinline__ uint32_t s2u(const void* p) {
    uint32_t a;
    asm("{ .reg .u64 t; cvta.to.shared.u64 t, %1; cvt.u32.u64 %0, t; }" : "=r"(a) : "l"(p));
    return a;
}
#define LDSM4(r0, r1, r2, r3, addr) \
    asm volatile("ldmatrix.sync.aligned.m8n8.x4.shared.b16 {%0,%1,%2,%3}, [%4];" \
                 : "=r"(r0), "=r"(r1), "=r"(r2), "=r"(r3) : "r"(addr))

// ---------------- k1: Tt = fp16((X @ W)^T) ----------------
__global__ void k_xw(const float* __restrict__ X, const float* __restrict__ W) {
    extern __shared__ float sm[];
    float* ws = sm;              // [128*128] W
    float* xs = sm + 16384;      // [128] one row of X
    float* tl = sm + 16512;      // [128*33] transpose staging
    int j = threadIdx.x;
    for (int i = j; i < 16384; i += 128) ws[i] = W[i];
    int r0 = blockIdx.x * 32;
    __syncthreads();
    for (int rr = 0; rr < 32; rr++) {
        xs[j] = X[(size_t)(r0 + rr) * 128 + j];
        __syncthreads();
        float acc = 0.f;
        #pragma unroll 16
        for (int k = 0; k < 128; k++) acc += xs[k] * ws[k * 128 + j];
        tl[j * 33 + rr] = acc;
        __syncthreads();
    }
    for (int idx = j; idx < 4096; idx += 128) {
        int jj = idx >> 5, r2 = idx & 31;
        g_Th[(size_t)jj * NR + r0 + r2] = __float2half_rn(tl[jj * 33 + r2]);
    }
}

// ---------------- k2: H = A @ T, fp16 mma.sync, single-sync pipeline ----------------
__global__ void __launch_bounds__(256, 1) k_gemm(const float* __restrict__ A) {
    extern __shared__ __align__(16) char smc[];
    const int tid = threadIdx.x, wid = tid >> 5, lid = tid & 31;
    const int gid = lid >> 2, tig = lid & 3;
    const int m0 = blockIdx.x * 128;
    const int wm = (wid & 1) * 64;      // warps 2(M) x 4(N), warp tile 64x32
    const int wn = (wid >> 1) * 32;
    const uint32_t smb = s2u(smc);

    // per-lane ldmatrix base offsets (stage-relative)
    const uint32_t aoff = A16OFF + (uint32_t)(wm + (lid & 15)) * 80u + ((lid >> 4) * 16u);
    const uint32_t boff = B16OFF + (uint32_t)(wn + ((lid & 16) >> 1) + (lid & 7)) * 80u
                        + ((lid & 8) ? 16u : 0u);

    // load chunk ch into stage st (each thread: 4 A-segs then 2 B-segs, 16B each)
    auto load = [&](int ch, int st) {
        uint32_t base = smb + (uint32_t)st * STGB;
        #pragma unroll
        for (int it = 0; it < 4; it++) {          // A: 1024 x 16B fp32
            int u = tid + it * 256, row = u >> 3, s = u & 7;
            uint32_t dst = base + A32OFF + row * 144 + s * 16;
            const float* gp = A + (size_t)(m0 + row) * NR + (size_t)ch * 32 + s * 4;
            asm volatile("cp.async.cg.shared.global [%0], [%1], 16;" :: "r"(dst), "l"(gp));
        }
        #pragma unroll
        for (int it = 0; it < 2; it++) {          // B: 512 x 16B fp16
            int v = tid + it * 256, n = v >> 2, s = v & 3;
            uint32_t dst = base + B16OFF + n * 80 + s * 16;
            const __half* gp = g_Th + (size_t)n * NR + (size_t)ch * 32 + s * 8;
            asm volatile("cp.async.cg.shared.global [%0], [%1], 16;" :: "r"(dst), "l"(gp));
        }
        asm volatile("cp.async.commit_group;" ::: "memory");
    };
    // each thread converts exactly the A-segments IT loaded (wait_group-only visibility)
    auto convertA = [&](int ch) {
        char* base = smc + (ch & 3) * STGB;
        #pragma unroll
        for (int it = 0; it < 4; it++) {
            int u = tid + it * 256, row = u >> 3, s = u & 7;
            float4 f = *(const float4*)(base + A32OFF + row * 144 + s * 16);
            __half2 h0 = __floats2half2_rn(f.x, f.y);
            __half2 h1 = __floats2half2_rn(f.z, f.w);
            uint2 uu;
            uu.x = *reinterpret_cast<unsigned*>(&h0);
            uu.y = *reinterpret_cast<unsigned*>(&h1);
            *(uint2*)(base + A16OFF + row * 80 + s * 8) = uu;
        }
    };

    float c[4][4][4];
    #pragma unroll
    for (int i = 0; i < 4; i++)
        #pragma unroll
        for (int j = 0; j < 4; j++)
            c[i][j][0] = c[i][j][1] = c[i][j][2] = c[i][j][3] = 0.f;

    load(0, 0); load(1, 1); load(2, 2);
    asm volatile("cp.async.wait_group 2;" ::: "memory");
    convertA(0);

    for (int ch = 0; ch < 512; ch++) {
        __syncthreads();   // publishes convertA(ch) + B16(ch); frees stage (ch-1)&3
        if (ch + 3 < 512) load(ch + 3, (ch + 3) & 3);
        else asm volatile("cp.async.commit_group;" ::: "memory");
        asm volatile("cp.async.wait_group 2;" ::: "memory");   // own chunk ch+1 segs arrived
        if (ch + 1 < 512) convertA(ch + 1);

        const uint32_t sbu = smb + (ch & 3) * STGB;
        #pragma unroll
        for (int ks = 0; ks < 2; ks++) {
            uint32_t a[4][4], b[4][2];
            #pragma unroll
            for (int i = 0; i < 4; i++)
                LDSM4(a[i][0], a[i][1], a[i][2], a[i][3], sbu + aoff + i * 1280u + ks * 32u);
            #pragma unroll
            for (int jp = 0; jp < 2; jp++)
                LDSM4(b[2*jp][0], b[2*jp][1], b[2*jp+1][0], b[2*jp+1][1],
                      sbu + boff + jp * 1280u + ks * 32u);
            #pragma unroll
            for (int i = 0; i < 4; i++)
                #pragma unroll
                for (int j = 0; j < 4; j++)
                    asm volatile(
                        "mma.sync.aligned.m16n8k16.row.col.f32.f16.f16.f32 "
                        "{%0,%1,%2,%3}, {%4,%5,%6,%7}, {%8,%9}, {%0,%1,%2,%3};"
                        : "+f"(c[i][j][0]), "+f"(c[i][j][1]),
                          "+f"(c[i][j][2]), "+f"(c[i][j][3])
                        : "r"(a[i][0]), "r"(a[i][1]), "r"(a[i][2]), "r"(a[i][3]),
                          "r"(b[j][0]), "r"(b[j][1]));
        }
    }

    // epilogue 1: accumulators -> g_H
    #pragma unroll
    for (int i = 0; i < 4; i++)
        #pragma unroll
        for (int j = 0; j < 4; j++) {
            int row = m0 + wm + i * 16 + gid;
            int col = wn + j * 8 + tig * 2;
            *(float2*)&g_H[(size_t)row * 128 + col]       = make_float2(c[i][j][0], c[i][j][1]);
            *(float2*)&g_H[(size_t)(row + 8) * 128 + col] = make_float2(c[i][j][2], c[i][j][3]);
        }

    // epilogue 2: fused per-CTA column sums / sumsq (deterministic)
    float* sred = (float*)smc;          // [2][128]
    float* qred = sred + 256;           // [2][128]
    __syncthreads();                    // stage smem no longer needed
    #pragma unroll
    for (int j = 0; j < 4; j++) {
        float s0 = 0.f, s1 = 0.f, q0 = 0.f, q1 = 0.f;
        #pragma unroll
        for (int i = 0; i < 4; i++) {
            s0 += c[i][j][0] + c[i][j][2];
            s1 += c[i][j][1] + c[i][j][3];
            q0 += c[i][j][0] * c[i][j][0] + c[i][j][2] * c[i][j][2];
            q1 += c[i][j][1] * c[i][j][1] + c[i][j][3] * c[i][j][3];
        }
        #pragma unroll
        for (int m = 4; m <= 16; m <<= 1) {
            s0 += __shfl_xor_sync(0xffffffffu, s0, m);
            s1 += __shfl_xor_sync(0xffffffffu, s1, m);
            q0 += __shfl_xor_sync(0xffffffffu, q0, m);
            q1 += __shfl_xor_sync(0xffffffffu, q1, m);
        }
        if (gid == 0) {
            int col = wn + j * 8 + tig * 2;
            sred[(wid & 1) * 128 + col]     = s0;
            sred[(wid & 1) * 128 + col + 1] = s1;
            qred[(wid & 1) * 128 + col]     = q0;
            qred[(wid & 1) * 128 + col + 1] = q1;
        }
    }
    __syncthreads();
    if (tid < 128) {
        g_ps[blockIdx.x * 128 + tid] = sred[tid] + sred[128 + tid];
        g_pq[blockIdx.x * 128 + tid] = qred[tid] + qred[128 + tid];
    }
}

// ---------------- k_fin: mean / scale (1024 threads) ----------------
__global__ void k_fin(const float* __restrict__ gamma, const float* __restrict__ beta) {
    __shared__ float ss[8][128], qq[8][128];
    int t = threadIdx.x, j = t & 127, g = t >> 7;
    float s = 0.f, q = 0.f;
    #pragma unroll
    for (int b = g * 16; b < g * 16 + 16; b++) { s += g_ps[b * 128 + j]; q += g_pq[b * 128 + j]; }
    ss[g][j] = s; qq[g][j] = q;
    __syncthreads();
    if (t < 128) {
        float S = 0.f, Q = 0.f;
        #pragma unroll
        for (int g2 = 0; g2 < 8; g2++) { S += ss[g2][t]; Q += qq[g2][t]; }
        float m = S * (1.f / NR);
        float var = Q * (1.f / NR) - m * m;
        g_mean[t] = m;
        g_scale[t] = gamma[t] * rsqrtf(var + 1e-5f);
        g_beta2[t] = beta[t];
    }
}

// ---------------- k_apply: BN + LeakyReLU ----------------
__global__ void k_apply(float* __restrict__ out) {
    size_t i = (size_t)blockIdx.x * blockDim.x + threadIdx.x;   // float4 units
    int c = ((int)(i & 31)) * 4;
    float4 h = ((const float4*)g_H)[i];
    float4 r; float t;
    t = (h.x - g_mean[c+0]) * g_scale[c+0] + g_beta2[c+0]; r.x = t >= 0.f ? t : 0.2f * t;
    t = (h.y - g_mean[c+1]) * g_scale[c+1] + g_beta2[c+1]; r.y = t >= 0.f ? t : 0.2f * t;
    t = (h.z - g_mean[c+2]) * g_scale[c+2] + g_beta2[c+2]; r.z = t >= 0.f ? t : 0.2f * t;
    t = (h.w - g_mean[c+3]) * g_scale[c+3] + g_beta2[c+3]; r.w = t >= 0.f ? t : 0.2f * t;
    ((float4*)out)[i] = r;
}

extern "C" void kernel_launch(void* const* d_in, const int* in_sizes, int n_in,
                              void* d_out, int out_size) {
    const float* x     = (const float*)d_in[0];
    const float* A     = (const float*)d_in[1];
    const float* W     = (const float*)d_in[2];
    // d_in[3] = bias b: per-column constant, cancels exactly under BatchNorm -> unused
    const float* gamma = (const float*)d_in[4];
    const float* beta  = (const float*)d_in[5];
    float* out = (float*)d_out;

    cudaFuncSetAttribute(k_xw,   cudaFuncAttributeMaxDynamicSharedMemorySize, 82944);
    cudaFuncSetAttribute(k_gemm, cudaFuncAttributeMaxDynamicSharedMemorySize, 4 * STGB);

    k_xw   <<<512, 128, 82944>>>(x, W);
    k_gemm <<<128, 256, 4 * STGB>>>(A);
    k_fin  <<<1, 1024>>>(gamma, beta);
    k_apply<<<2048, 256>>>(out);
}